// round 7
// baseline (speedup 1.0000x reference)
#include <cuda_runtime.h>
#include <cuda_bf16.h>
#include <cstdint>

#define NN 256
#define FF 16
#define HH 2048
#define PP 16
#define EE 32768

// Scratch (device globals; allocation is forbidden).
__device__ int4  d_A4[NN * NN / 4];   // dense count matrix (incl. self-loops), 256 KB
__device__ int   d_deg[NN];
__device__ float d_outh[NN * HH];     // agg @ W + b   (2 MB)

// ---------------------------------------------------------------------------
// K0: init A to identity (self-loops on the diagonal) and deg to 1.
// 64 blocks x 256 threads, int4 stores.
// ---------------------------------------------------------------------------
__global__ __launch_bounds__(256) void k_init(const float* __restrict__ dummy) {
    int i = blockIdx.x * 256 + threadIdx.x;     // 16384 int4 over 65536 ints
    int row = i >> 6;                            // 64 int4 per row
    int4 v = make_int4(0, 0, 0, 0);
    if ((i & 63) == (row >> 2)) {               // this int4 holds the diagonal
        int c = row & 3;
        if (c == 0) v.x = 1; else if (c == 1) v.y = 1;
        else if (c == 2) v.z = 1; else v.w = 1;
    }
    d_A4[i] = v;
    if (i < NN) d_deg[i] = 1;                    // self-loop contributes 1
    (void)dummy;
}

// ---------------------------------------------------------------------------
// K1: one edge per thread; spread global atomics (64K addresses -> ~no
// contention on A; deg is 128/address, parallel across L2 partitions).
// Edge dtype probed at runtime (harness delivers int64 cast to int32).
// ---------------------------------------------------------------------------
__global__ __launch_bounds__(256) void k_edges(const void* __restrict__ ei_raw) {
    const int*       e32 = (const int*)ei_raw;
    const long long* e64 = (const long long*)ei_raw;

    int probe = 0;
#pragma unroll
    for (int k = 0; k < 16; k++) probe |= e32[2 * k + 1];
    const bool is64 = (probe == 0);

    int e = blockIdx.x * 256 + threadIdx.x;      // 128 blocks -> e in [0, EE)
    int src, dst;
    if (is64) { src = (int)e64[e]; dst = (int)e64[EE + e]; }
    else      { src = e32[e];      dst = e32[EE + e];      }

    if ((unsigned)src < (unsigned)NN && (unsigned)dst < (unsigned)NN) {
        int* A = reinterpret_cast<int*>(d_A4);
        atomicAdd(&A[dst * NN + src], 1);
        atomicAdd(&d_deg[dst], 1);
    }
}

// ---------------------------------------------------------------------------
// K2 (fused): dinv from deg, agg for this block's 16-node chunk, then
// out[n,h] = b[h] + sum_f agg[n,f]*W[f,h]. Block (ht, nc), grid (8, 16).
// ht==0 blocks also pre-initialize q = bq for K3's atomic accumulation.
// ---------------------------------------------------------------------------
__global__ __launch_bounds__(256) void k_fused(const float* __restrict__ x,
                                               const float* __restrict__ W,
                                               const float* __restrict__ bias,
                                               const float* __restrict__ bq,
                                               float* __restrict__ q) {
    __shared__ float sdinv[NN];       // 1 KB
    __shared__ float sy[NN * FF];     // 16 KB (dinv-scaled x)
    __shared__ int   sA[16 * NN];     // 16 KB
    __shared__ float sagg[256];       // 1 KB (16 nodes x 16 f)
    int t  = threadIdx.x;
    int ht = blockIdx.x;
    int nc = blockIdx.y;

    // q init (nc covers exactly 16 nodes x 16 p = 256 values)
    if (ht == 0) q[nc * 256 + t] = bq[nc * 256 + t];

    // dinv for all nodes (deg >= 1 always)
    sdinv[t] = rsqrtf((float)d_deg[t]);

    // stage this chunk's 16 A-rows (1024 int4)
    int4* sA4 = reinterpret_cast<int4*>(sA);
#pragma unroll
    for (int i = 0; i < 4; i++) {
        int j = t + i * 256;
        sA4[j] = d_A4[nc * 1024 + j];
    }
    __syncthreads();

    // stage y = dinv * x  (float4 j covers row j>>2; FF=16 -> 4 float4/row)
    const float4* gx4 = reinterpret_cast<const float4*>(x);
    float4* sy4 = reinterpret_cast<float4*>(sy);
#pragma unroll
    for (int i = 0; i < 4; i++) {
        int j = t + i * 256;
        float dv = sdinv[j >> 2];
        float4 v = gx4[j];
        v.x *= dv; v.y *= dv; v.z *= dv; v.w *= dv;
        sy4[j] = v;
    }
    __syncthreads();

    // agg[dl,f] = dinv[d] * sum_s A[dl,s]*sy[s,f]
    {
        int dl = t >> 4, f = t & 15;
        float acc = 0.0f;
#pragma unroll 8
        for (int s = 0; s < NN; s++)
            acc += (float)sA[dl * NN + s] * sy[s * FF + f];
        sagg[t] = sdinv[nc * 16 + dl] * acc;
    }
    __syncthreads();

    // out for 16 nodes x 256 h
    int h = ht * 256 + t;
    float wc[FF];
#pragma unroll
    for (int f = 0; f < FF; f++) wc[f] = W[f * HH + h];
    float bh = bias[h];
#pragma unroll
    for (int nl = 0; nl < 16; nl++) {
        float v = bh;
#pragma unroll
        for (int f = 0; f < FF; f++) v = fmaf(sagg[nl * FF + f], wc[f], v);
        d_outh[(nc * 16 + nl) * HH + h] = v;
    }
}

// ---------------------------------------------------------------------------
// K3: q[n,p] += sum_h out[n,h] * Wq[n,h,p]
// 512 blocks (node, H-half) x 512 threads. Partials via atomicAdd.
// ---------------------------------------------------------------------------
__global__ __launch_bounds__(512) void k_final(const float* __restrict__ Wq,
                                               float* __restrict__ q) {
    __shared__ float sred[16 * PP];
    int n    = blockIdx.x >> 1;
    int half = blockIdx.x & 1;
    int t    = threadIdx.x;

    float acc[PP];
#pragma unroll
    for (int p = 0; p < PP; p++) acc[p] = 0.0f;

    const float* wqn = Wq + (size_t)n * HH * PP;
#pragma unroll
    for (int r = 0; r < 2; r++) {
        int h = half * 1024 + r * 512 + t;
        float oh = d_outh[n * HH + h];
        const float4* wq4 = reinterpret_cast<const float4*>(wqn + (size_t)h * PP);
        float4 a0 = wq4[0], a1 = wq4[1], a2 = wq4[2], a3 = wq4[3];
        acc[0]  = fmaf(oh, a0.x, acc[0]);  acc[1]  = fmaf(oh, a0.y, acc[1]);
        acc[2]  = fmaf(oh, a0.z, acc[2]);  acc[3]  = fmaf(oh, a0.w, acc[3]);
        acc[4]  = fmaf(oh, a1.x, acc[4]);  acc[5]  = fmaf(oh, a1.y, acc[5]);
        acc[6]  = fmaf(oh, a1.z, acc[6]);  acc[7]  = fmaf(oh, a1.w, acc[7]);
        acc[8]  = fmaf(oh, a2.x, acc[8]);  acc[9]  = fmaf(oh, a2.y, acc[9]);
        acc[10] = fmaf(oh, a2.z, acc[10]); acc[11] = fmaf(oh, a2.w, acc[11]);
        acc[12] = fmaf(oh, a3.x, acc[12]); acc[13] = fmaf(oh, a3.y, acc[13]);
        acc[14] = fmaf(oh, a3.z, acc[14]); acc[15] = fmaf(oh, a3.w, acc[15]);
    }

#pragma unroll
    for (int off = 16; off > 0; off >>= 1) {
#pragma unroll
        for (int p = 0; p < PP; p++)
            acc[p] += __shfl_down_sync(0xffffffffu, acc[p], off);
    }
    int wid  = t >> 5;
    int lane = t & 31;
    if (lane == 0) {
#pragma unroll
        for (int p = 0; p < PP; p++) sred[wid * PP + p] = acc[p];
    }
    __syncthreads();
    if (t < PP) {
        float s = 0.0f;
#pragma unroll
        for (int w = 0; w < 16; w++) s += sred[w * PP + t];
        atomicAdd(&q[n * PP + t], s);
    }
}

// ---------------------------------------------------------------------------
extern "C" void kernel_launch(void* const* d_in, const int* in_sizes, int n_in,
                              void* d_out, int out_size) {
    const float* x    = (const float*)d_in[0];      // [256,16]
    const void*  ei   = d_in[1];                    // [2,32768] (int64 cast to int32)
    const float* W    = (const float*)d_in[2];      // [16,2048]
    const float* bias = (const float*)d_in[3];      // [2048]
    const float* Wq   = (const float*)d_in[4];      // [256,2048,16]
    const float* bq   = (const float*)d_in[5];      // [256,16]
    float*       q    = (float*)d_out;              // [256,16]

    k_init<<<64, 256>>>(x);
    k_edges<<<EE / 256, 256>>>(ei);
    k_fused<<<dim3(8, 16), 256>>>(x, W, bias, bq, q);
    k_final<<<2 * NN, 512>>>(Wq, q);
}

// round 8
// speedup vs baseline: 1.2936x; 1.2936x over previous
#include <cuda_runtime.h>
#include <cuda_bf16.h>
#include <cstdint>

#define NN 256
#define FF 16
#define HH 2048
#define PP 16
#define EE 32768

// Scratch (device globals; allocation is forbidden).
__device__ int4  d_A4[NN * NN / 4];   // dense count matrix (incl. self-loops), 256 KB
__device__ int   d_deg[NN];
__device__ float d_outh[NN * HH];     // agg @ W + b   (2 MB)

// ---------------------------------------------------------------------------
// K0: init A to identity (self-loops) and deg to 1. 64 blocks x 256 threads.
// ---------------------------------------------------------------------------
__global__ __launch_bounds__(256) void k_init(const float* __restrict__ dummy) {
    int i = blockIdx.x * 256 + threadIdx.x;     // 16384 int4 over 65536 ints
    int row = i >> 6;                            // 64 int4 per row
    int4 v = make_int4(0, 0, 0, 0);
    if ((i & 63) == (row >> 2)) {               // this int4 holds the diagonal
        int c = row & 3;
        if (c == 0) v.x = 1; else if (c == 1) v.y = 1;
        else if (c == 2) v.z = 1; else v.w = 1;
    }
    d_A4[i] = v;
    if (i < NN) d_deg[i] = 1;                    // self-loop contributes 1
    (void)dummy;
}

// ---------------------------------------------------------------------------
// K1: one edge per thread; spread global atomics.
// Edge dtype probed at runtime (harness delivers int64 cast to int32).
// ---------------------------------------------------------------------------
__global__ __launch_bounds__(256) void k_edges(const void* __restrict__ ei_raw) {
    const int*       e32 = (const int*)ei_raw;
    const long long* e64 = (const long long*)ei_raw;

    int probe = 0;
#pragma unroll
    for (int k = 0; k < 16; k++) probe |= e32[2 * k + 1];
    const bool is64 = (probe == 0);

    int e = blockIdx.x * 256 + threadIdx.x;      // 128 blocks -> e in [0, EE)
    int src, dst;
    if (is64) { src = (int)e64[e]; dst = (int)e64[EE + e]; }
    else      { src = e32[e];      dst = e32[EE + e];      }

    if ((unsigned)src < (unsigned)NN && (unsigned)dst < (unsigned)NN) {
        int* A = reinterpret_cast<int*>(d_A4);
        atomicAdd(&A[dst * NN + src], 1);
        atomicAdd(&d_deg[dst], 1);
    }
}

// ---------------------------------------------------------------------------
// K2 (fused): dinv from deg, agg for this block's 16-node chunk, then
// out[n,h] = b[h] + sum_f agg[n,f]*W[f,h]. Block (ht, nc), grid (8, 16).
// ht==0 blocks also pre-initialize q = bq for K3's atomic accumulation.
// ---------------------------------------------------------------------------
__global__ __launch_bounds__(256) void k_fused(const float* __restrict__ x,
                                               const float* __restrict__ W,
                                               const float* __restrict__ bias,
                                               const float* __restrict__ bq,
                                               float* __restrict__ q) {
    __shared__ float sdinv[NN];       // 1 KB
    __shared__ float sy[NN * FF];     // 16 KB (dinv-scaled x)
    __shared__ int   sA[16 * NN];     // 16 KB
    __shared__ float sagg[256];       // 1 KB (16 nodes x 16 f)
    int t  = threadIdx.x;
    int ht = blockIdx.x;
    int nc = blockIdx.y;

    // q init (nc covers exactly 16 nodes x 16 p = 256 values)
    if (ht == 0) q[nc * 256 + t] = bq[nc * 256 + t];

    // dinv for all nodes (deg >= 1 always)
    sdinv[t] = rsqrtf((float)d_deg[t]);

    // stage this chunk's 16 A-rows (1024 int4)
    int4* sA4 = reinterpret_cast<int4*>(sA);
#pragma unroll
    for (int i = 0; i < 4; i++) {
        int j = t + i * 256;
        sA4[j] = d_A4[nc * 1024 + j];
    }
    __syncthreads();

    // stage y = dinv * x  (float4 j covers row j>>2; FF=16 -> 4 float4/row)
    const float4* gx4 = reinterpret_cast<const float4*>(x);
    float4* sy4 = reinterpret_cast<float4*>(sy);
#pragma unroll
    for (int i = 0; i < 4; i++) {
        int j = t + i * 256;
        float dv = sdinv[j >> 2];
        float4 v = gx4[j];
        v.x *= dv; v.y *= dv; v.z *= dv; v.w *= dv;
        sy4[j] = v;
    }
    __syncthreads();

    // agg[dl,f] = dinv[d] * sum_s A[dl,s]*sy[s,f]
    {
        int dl = t >> 4, f = t & 15;
        float acc = 0.0f;
#pragma unroll 8
        for (int s = 0; s < NN; s++)
            acc += (float)sA[dl * NN + s] * sy[s * FF + f];
        sagg[t] = sdinv[nc * 16 + dl] * acc;
    }
    __syncthreads();

    // out for 16 nodes x 256 h
    int h = ht * 256 + t;
    float wc[FF];
#pragma unroll
    for (int f = 0; f < FF; f++) wc[f] = W[f * HH + h];
    float bh = bias[h];
#pragma unroll
    for (int nl = 0; nl < 16; nl++) {
        float v = bh;
#pragma unroll
        for (int f = 0; f < FF; f++) v = fmaf(sagg[nl * FF + f], wc[f], v);
        d_outh[(nc * 16 + nl) * HH + h] = v;
    }
}

// ---------------------------------------------------------------------------
// K3: q[n,p] += sum_h out[n,h] * Wq[n,h,p], warp-contiguous Wq walk.
// Flattened float4 view per node: idx -> h = idx>>2, p-group = (idx&3)*4.
// Warp accesses 32 consecutive float4 = 512B = 4 lines (minimal wavefronts).
// Grid 512 = (node, H-half); 512 threads; 4 accumulators per thread.
// ---------------------------------------------------------------------------
__global__ __launch_bounds__(512) void k_final(const float* __restrict__ Wq,
                                               float* __restrict__ q) {
    __shared__ float s_oh[1024];      // this block's outh half-row (4 KB)
    __shared__ float sred[16 * PP];   // per-warp partials
    int n    = blockIdx.x >> 1;
    int half = blockIdx.x & 1;
    int t    = threadIdx.x;

    if (t < 256)
        reinterpret_cast<float4*>(s_oh)[t] =
            reinterpret_cast<const float4*>(d_outh + n * HH + half * 1024)[t];
    __syncthreads();

    const float4* wq4 = reinterpret_cast<const float4*>(Wq)
                      + (size_t)n * (HH * PP / 4) + half * 4096;

    float a0 = 0.f, a1 = 0.f, a2 = 0.f, a3 = 0.f;
#pragma unroll
    for (int r = 0; r < 8; r++) {
        int idx = r * 512 + t;        // warp covers 32 consecutive float4
        float4 v = wq4[idx];
        float oh = s_oh[idx >> 2];
        a0 = fmaf(oh, v.x, a0);
        a1 = fmaf(oh, v.y, a1);
        a2 = fmaf(oh, v.z, a2);
        a3 = fmaf(oh, v.w, a3);
    }

    // reduce over lanes congruent mod 4 (p-group fixed = (lane&3)*4)
#pragma unroll
    for (int off = 16; off >= 4; off >>= 1) {
        a0 += __shfl_down_sync(0xffffffffu, a0, off);
        a1 += __shfl_down_sync(0xffffffffu, a1, off);
        a2 += __shfl_down_sync(0xffffffffu, a2, off);
        a3 += __shfl_down_sync(0xffffffffu, a3, off);
    }
    int lane = t & 31, wid = t >> 5;
    if (lane < 4) {
        sred[wid * PP + lane * 4 + 0] = a0;
        sred[wid * PP + lane * 4 + 1] = a1;
        sred[wid * PP + lane * 4 + 2] = a2;
        sred[wid * PP + lane * 4 + 3] = a3;
    }
    __syncthreads();
    if (t < PP) {
        float s = 0.0f;
#pragma unroll
        for (int w = 0; w < 16; w++) s += sred[w * PP + t];
        atomicAdd(&q[n * PP + t], s);
    }
}

// ---------------------------------------------------------------------------
extern "C" void kernel_launch(void* const* d_in, const int* in_sizes, int n_in,
                              void* d_out, int out_size) {
    const float* x    = (const float*)d_in[0];      // [256,16]
    const void*  ei   = d_in[1];                    // [2,32768] (int64 cast to int32)
    const float* W    = (const float*)d_in[2];      // [16,2048]
    const float* bias = (const float*)d_in[3];      // [2048]
    const float* Wq   = (const float*)d_in[4];      // [256,2048,16]
    const float* bq   = (const float*)d_in[5];      // [256,16]
    float*       q    = (float*)d_out;              // [256,16]

    k_init<<<64, 256>>>(x);
    k_edges<<<EE / 256, 256>>>(ei);
    k_fused<<<dim3(8, 16), 256>>>(x, W, bias, bq, q);
    k_final<<<2 * NN, 512>>>(Wq, q);
}

// round 10
// speedup vs baseline: 1.3924x; 1.0763x over previous
#include <cuda_runtime.h>
#include <cuda_bf16.h>
#include <cstdint>

#define NN 256
#define FF 16
#define HH 2048
#define PP 16
#define EE 32768

// Scratch (device globals; allocation is forbidden).
__device__ int4 d_A4[NN * NN / 4];    // dense count matrix (incl. self-loops), 256 KB
__device__ int  d_deg[NN];

// ---------------------------------------------------------------------------
// K0: A = I (self-loops), deg = 1, q = bq. 64 blocks x 256 threads.
// ---------------------------------------------------------------------------
__global__ __launch_bounds__(256) void k_init(const float* __restrict__ bq,
                                              float* __restrict__ q) {
    int i = blockIdx.x * 256 + threadIdx.x;     // 16384 int4 over 65536 ints
    int row = i >> 6;                            // 64 int4 per row
    int4 v = make_int4(0, 0, 0, 0);
    if ((i & 63) == (row >> 2)) {               // this int4 holds the diagonal
        int c = row & 3;
        if (c == 0) v.x = 1; else if (c == 1) v.y = 1;
        else if (c == 2) v.z = 1; else v.w = 1;
    }
    d_A4[i] = v;
    if (i < NN) d_deg[i] = 1;                    // self-loop contributes 1
    if (i < NN * PP) q[i] = bq[i];               // bias for the atomic epilogue
}

// ---------------------------------------------------------------------------
// K1: one edge per thread; spread global atomics.
// Edge dtype probed at runtime (harness delivers int64 cast to int32).
// ---------------------------------------------------------------------------
__global__ __launch_bounds__(256) void k_edges(const void* __restrict__ ei_raw) {
    const int*       e32 = (const int*)ei_raw;
    const long long* e64 = (const long long*)ei_raw;

    int probe = 0;
#pragma unroll
    for (int k = 0; k < 16; k++) probe |= e32[2 * k + 1];
    const bool is64 = (probe == 0);

    int e = blockIdx.x * 256 + threadIdx.x;      // 128 blocks -> e in [0, EE)
    int src, dst;
    if (is64) { src = (int)e64[e]; dst = (int)e64[EE + e]; }
    else      { src = e32[e];      dst = e32[EE + e];      }

    if ((unsigned)src < (unsigned)NN && (unsigned)dst < (unsigned)NN) {
        int* A = reinterpret_cast<int*>(d_A4);
        atomicAdd(&A[dst * NN + src], 1);
        atomicAdd(&d_deg[dst], 1);
    }
}

// ---------------------------------------------------------------------------
// K2 (mega): block (n, half) recomputes agg[n,:] and its out half-row from
// L2-resident inputs, then streams Wq (the only DRAM-sized read).
//   agg[f]  = dinv[n] * sum_s A[n,s] * dinv[s] * x[s,f]
//   oh[hl]  = bias[h] + sum_f agg[f] * W[f,h],   h = half*1024 + hl
//   q[n,p] += sum_h oh[h] * Wq[n,h,p]            (atomic, 2 halves)
// ---------------------------------------------------------------------------
__global__ __launch_bounds__(512) void k_mega(const float* __restrict__ x,
                                              const float* __restrict__ W,
                                              const float* __restrict__ bias,
                                              const float* __restrict__ Wq,
                                              float* __restrict__ q) {
    __shared__ float sdinv[NN];       // 1 KB
    __shared__ float sy[NN * FF];     // 16 KB (dinv-scaled x)
    __shared__ int   sArow[NN];       // 1 KB (A row n)
    __shared__ float spart[512];      // 2 KB (agg partials)
    __shared__ float sagg[FF];
    __shared__ float s_oh[1024];      // 4 KB (out half-row)
    __shared__ float sred[16 * PP];   // 1 KB

    int n    = blockIdx.x >> 1;
    int half = blockIdx.x & 1;
    int t    = threadIdx.x;

    // --- stage dinv and A row n ---
    if (t < NN) sdinv[t] = rsqrtf((float)d_deg[t]);
    else if (t < NN + 64) reinterpret_cast<int4*>(sArow)[t - NN] = d_A4[n * 64 + (t - NN)];
    __syncthreads();

    // --- stage sy = dinv * x (1024 float4; 2 per thread) ---
    const float4* gx4 = reinterpret_cast<const float4*>(x);
    float4* sy4 = reinterpret_cast<float4*>(sy);
#pragma unroll
    for (int i = 0; i < 2; i++) {
        int j = t + i * 512;
        float dv = sdinv[j >> 2];
        float4 v = gx4[j];
        v.x *= dv; v.y *= dv; v.z *= dv; v.w *= dv;
        sy4[j] = v;
    }
    __syncthreads();

    // --- agg partials: thread (f = t&15, g = t>>4) covers 8 src nodes ---
    {
        int f = t & 15, g = t >> 4;
        float p = 0.0f;
#pragma unroll
        for (int k = 0; k < 8; k++) {
            int s = g * 8 + k;
            p += (float)sArow[s] * sy[s * FF + f];
        }
        spart[t] = p;
    }
    __syncthreads();
    if (t < FF) {
        float a = 0.0f;
#pragma unroll
        for (int g = 0; g < 32; g++) a += spart[g * FF + t];
        sagg[t] = a * sdinv[n];
    }
    __syncthreads();

    // --- out half-row: 1024 h, 2 per thread; W reads are L2 hits ---
#pragma unroll
    for (int i = 0; i < 2; i++) {
        int hl = t + i * 512;
        int h  = half * 1024 + hl;
        float v = bias[h];
#pragma unroll
        for (int f = 0; f < FF; f++) v = fmaf(sagg[f], W[f * HH + h], v);
        s_oh[hl] = v;
    }
    __syncthreads();

    // --- Wq stream: warp-contiguous float4 walk (idx -> h=idx>>2, pg=(idx&3)*4)
    const float4* wq4 = reinterpret_cast<const float4*>(Wq)
                      + (size_t)n * (HH * PP / 4) + half * 4096;
    float a0 = 0.f, a1 = 0.f, a2 = 0.f, a3 = 0.f;
#pragma unroll
    for (int r = 0; r < 8; r++) {
        int idx = r * 512 + t;        // warp covers 32 consecutive float4
        float4 v = wq4[idx];
        float oh = s_oh[idx >> 2];
        a0 = fmaf(oh, v.x, a0);
        a1 = fmaf(oh, v.y, a1);
        a2 = fmaf(oh, v.z, a2);
        a3 = fmaf(oh, v.w, a3);
    }

    // --- reduce over lanes congruent mod 4 (p-group fixed = (lane&3)*4) ---
#pragma unroll
    for (int off = 16; off >= 4; off >>= 1) {
        a0 += __shfl_down_sync(0xffffffffu, a0, off);
        a1 += __shfl_down_sync(0xffffffffu, a1, off);
        a2 += __shfl_down_sync(0xffffffffu, a2, off);
        a3 += __shfl_down_sync(0xffffffffu, a3, off);
    }
    int lane = t & 31, wid = t >> 5;
    if (lane < 4) {
        sred[wid * PP + lane * 4 + 0] = a0;
        sred[wid * PP + lane * 4 + 1] = a1;
        sred[wid * PP + lane * 4 + 2] = a2;
        sred[wid * PP + lane * 4 + 3] = a3;
    }
    __syncthreads();
    if (t < PP) {
        float s = 0.0f;
#pragma unroll
        for (int w = 0; w < 16; w++) s += sred[w * PP + t];
        atomicAdd(&q[n * PP + t], s);
    }
}

// ---------------------------------------------------------------------------
extern "C" void kernel_launch(void* const* d_in, const int* in_sizes, int n_in,
                              void* d_out, int out_size) {
    const float* x    = (const float*)d_in[0];      // [256,16]
    const void*  ei   = d_in[1];                    // [2,32768] (int64 cast to int32)
    const float* W    = (const float*)d_in[2];      // [16,2048]
    const float* bias = (const float*)d_in[3];      // [2048]
    const float* Wq   = (const float*)d_in[4];      // [256,2048,16]
    const float* bq   = (const float*)d_in[5];      // [256,16]
    float*       q    = (float*)d_out;              // [256,16]

    k_init<<<64, 256>>>(bq, q);
    k_edges<<<EE / 256, 256>>>(ei);
    k_mega<<<2 * NN, 512>>>(x, W, bias, Wq, q);
}